// round 5
// baseline (speedup 1.0000x reference)
#include <cuda_runtime.h>

#define Bsz  512
#define Ssz  2688
#define Fsz  32
#define Hsz  512
#define WEEK 672
#define NCTA 128
#define NTHR 256

#define AROW64 34    // sA row stride in u64 (272B: 16B-aligned, 128-phase rotating)
#define WROW64 130   // sW row stride in u64 (1040B: 16B-aligned, 128-phase rotating)
#define AROWF  (AROW64 * 2)
#define SGROWF 66    // gate-exchange row stride (floats)

typedef unsigned long long u64;

// ---------------- persistent state (device globals; no allocation) ----------
__device__ float d_h0[2][Bsz * Hsz];
__device__ float d_c0[Bsz * Hsz];
__device__ float d_h1[2][Bsz * Hsz];
__device__ float d_c1[Bsz * Hsz];
__device__ float d_bsum0[4 * Hsz];
__device__ float d_bsum1[4 * Hsz];
__device__ unsigned d_bar;

__device__ __forceinline__ float sigm(float x) { return 1.f / (1.f + expf(-x)); }

__device__ __forceinline__ u64 fma2(u64 a, u64 b, u64 c) {
    u64 d;
    asm("fma.rn.f32x2 %0, %1, %2, %3;" : "=l"(d) : "l"(a), "l"(b), "l"(c));
    return d;
}
__device__ __forceinline__ u64 pack2(float lo, float hi) {
    u64 d;
    asm("mov.b64 %0, {%1, %2};" : "=l"(d) : "f"(lo), "f"(hi));
    return d;
}
__device__ __forceinline__ float2 unpack2(u64 v) {
    float lo, hi;
    asm("mov.b64 {%0, %1}, %2;" : "=f"(lo), "=f"(hi) : "l"(v));
    return make_float2(lo, hi);
}

// release/acquire device-wide barrier (128 CTAs, 1 per SM)
__device__ __forceinline__ void gsync() {
    __syncthreads();
    if (threadIdx.x == 0) {
        unsigned old, cur, one = 1u;
        asm volatile("atom.release.gpu.add.u32 %0, [%1], %2;"
                     : "=r"(old) : "l"(&d_bar), "r"(one) : "memory");
        unsigned target = (old / NCTA + 1u) * NCTA;
        do {
            asm volatile("ld.acquire.gpu.u32 %0, [%1];"
                         : "=r"(cur) : "l"(&d_bar) : "memory");
        } while (cur < target);
    }
    __syncthreads();
}

// ---------------- init ------------------------------------------------------
__global__ void init_state(const float* __restrict__ bih0, const float* __restrict__ bhh0,
                           const float* __restrict__ bih1, const float* __restrict__ bhh1) {
    int i = blockIdx.x * blockDim.x + threadIdx.x;
    if (i < Bsz * Hsz) {
        d_h0[0][i] = 0.f; d_h0[1][i] = 0.f; d_c0[i] = 0.f;
        d_h1[0][i] = 0.f; d_h1[1][i] = 0.f; d_c1[i] = 0.f;
    }
    if (i < 4 * Hsz) {
        d_bsum0[i] = bih0[i] + bhh0[i];
        d_bsum1[i] = bih1[i] + bhh1[i];
    }
    if (i == 0) d_bar = 0u;
}

// ---------------- inner product: 8m (4 packed u64) x 4gc per thread ----------
// sA64[k][m-pair]: natural float pairs (a_2p, a_2p+1).
// sW64[k][gc]: duplicated (w,w) — FFMA2-ready, zero per-k packs.
template <int KT>
__device__ __forceinline__ void fma_tile(const u64* __restrict__ sA64,
                                         const u64* __restrict__ sW64,
                                         int mb4, int jgc4, u64 acc[4][4]) {
#pragma unroll 8
    for (int k = 0; k < KT; k++) {
        u64 av[4], wv[4];
#pragma unroll
        for (int p = 0; p < 4; p++) av[p] = sA64[k * AROW64 + mb4 + p];
#pragma unroll
        for (int j = 0; j < 4; j++) wv[j] = sW64[k * WROW64 + jgc4 + j];
#pragma unroll
        for (int j = 0; j < 4; j++)
#pragma unroll
            for (int p = 0; p < 4; p++)
                acc[j][p] = fma2(av[p], wv[j], acc[j][p]);
    }
}

// ---------------- the persistent kernel --------------------------------------
__global__ __launch_bounds__(NTHR, 1) void run_all(
    const float* __restrict__ x,
    const float* __restrict__ Wih0, const float* __restrict__ Whh0,
    const float* __restrict__ Wih1, const float* __restrict__ Whh1,
    const float* __restrict__ Wout, const float* __restrict__ bout,
    float* __restrict__ out) {
    __shared__ __align__(16) float sA[33 * AROWF];           //  8976 B
    __shared__ __align__(16) u64   sW64[33 * WROW64];        // 34320 B, reused as sG
    __shared__ float spred[64];

    float* sW = reinterpret_cast<float*>(sW64);
    const u64* sA64 = reinterpret_cast<const u64*>(sA);

    const int tid = threadIdx.x;
    const int mb = tid & 7;                 // m-block: m = mb*8 .. mb*8+7
    const int jgc = tid >> 3;               // gc group: gc = jgc*4 .. +3 (0..127)
    const int mb4 = mb * 4, jgc4 = jgc * 4;
    const int jt = blockIdx.x & 15, bt = blockIdx.x >> 4;
    const int bn = jt * 32, bm = bt * 64;
    const float bout0 = bout[0];

    float ra[8], rw[16];                    // gmem staging registers

    auto loadA = [&](const float* __restrict__ src, int kc) {
        int b = tid >> 2, kq = tid & 3;     // 8 consecutive k for one batch row
        const float4* p = reinterpret_cast<const float4*>(
            &src[(bm + b) * Hsz + kc * 32 + kq * 8]);
        *reinterpret_cast<float4*>(&ra[0]) = p[0];
        *reinterpret_cast<float4*>(&ra[4]) = p[1];
    };
    auto loadW = [&](const float* __restrict__ W, int kc) {
        int gc = tid >> 1, kh = tid & 1;    // 16 consecutive k for one gate-col
        int g = gc >> 5, j = gc & 31;
        const float4* p = reinterpret_cast<const float4*>(
            &W[(g * Hsz + bn + j) * Hsz + kc * 32 + kh * 16]);
#pragma unroll
        for (int q = 0; q < 4; q++) *reinterpret_cast<float4*>(&rw[q * 4]) = p[q];
    };
    auto storeAW = [&]() {
        int b = tid >> 2, kq = tid & 3;
#pragma unroll
        for (int u = 0; u < 8; u++) sA[(kq * 8 + u) * AROWF + b] = ra[u];
        int gc = tid >> 1, kh = tid & 1;
#pragma unroll
        for (int u = 0; u < 16; u++)
            sW64[(kh * 16 + u) * WROW64 + gc] = pack2(rw[u], rw[u]);
    };

    auto epilogue = [&](const float* __restrict__ bsum, float* __restrict__ cptr,
                        float* __restrict__ hdst, u64 acc[4][4]) {
        __syncthreads();                    // all warps done reading sW
        u64* sG64 = sW64;                   // overlay: 128 gc-rows x 33 u64 (66 floats)
#pragma unroll
        for (int j = 0; j < 4; j++)
#pragma unroll
            for (int p = 0; p < 4; p++)
                sG64[(jgc4 + j) * (SGROWF / 2) + mb4 + p] = acc[j][p];
        __syncthreads();
        const float* sG = reinterpret_cast<const float*>(sG64);
        int jl = tid & 31, bq = tid >> 5;   // 8 b-groups of 8
        float bi = bsum[bn + jl];
        float bf = bsum[512 + bn + jl];
        float bg = bsum[1024 + bn + jl];
        float bo = bsum[1536 + bn + jl];
#pragma unroll
        for (int u = 0; u < 8; u++) {
            int b = bq * 8 + u;
            float gi = sG[(jl) * SGROWF + b];
            float gf = sG[(32 + jl) * SGROWF + b];
            float gg = sG[(64 + jl) * SGROWF + b];
            float go = sG[(96 + jl) * SGROWF + b];
            float iv = sigm(gi + bi);
            float fv = sigm(gf + bf);
            float gv = tanhf(gg + bg);
            float ov = sigm(go + bo);
            int ci = (bm + b) * Hsz + bn + jl;
            float cn = fv * cptr[ci] + iv * gv;
            cptr[ci] = cn;
            hdst[ci] = ov * tanhf(cn);
        }
        __syncthreads();                    // sG free before buffers reused
    };

#pragma unroll 1
    for (int t = 0; t < Ssz; t++) {
        const bool use_orig = (((t / WEEK) & 1) == 0);
        const float* __restrict__ hsrc0 = d_h0[t & 1];
        float* __restrict__ hdst0 = d_h0[(t & 1) ^ 1];
        const float* __restrict__ hsrc1 = d_h1[t & 1];
        float* __restrict__ hdst1 = d_h1[(t & 1) ^ 1];

        // ---- out(t-1) = h1(t-1).Wout + bout ----
        if (t > 0 && (!use_orig || jt == 0)) {
            int b = tid >> 2;
            int k0 = (tid & 3) * 128;
            const float* hp = &hsrc1[(bm + b) * Hsz + k0];
            const float* wp = &Wout[k0];
            float s = 0.f;
#pragma unroll 8
            for (int k = 0; k < 128; k++) s += hp[k] * wp[k];
            s += __shfl_down_sync(0xffffffffu, s, 2);
            s += __shfl_down_sync(0xffffffffu, s, 1);
            if ((tid & 3) == 0) {
                float val = s + bout0;
                spred[b] = val;
                if (jt == 0) out[(bm + b) * Ssz + (t - 1)] = val;
            }
        }
        __syncthreads();

        // ================= layer 0 =================
        u64 acc[4][4];
#pragma unroll
        for (int j = 0; j < 4; j++)
#pragma unroll
            for (int p = 0; p < 4; p++) acc[j][p] = 0ull;

        // phase 1: K = 33 input features (feat0 | x[:,1:32] | flag)
        for (int idx = tid; idx < 64 * 33; idx += NTHR) {
            int b = idx / 33, f = idx - b * 33;
            int gb = bm + b;
            float v;
            if (f == 0)      v = use_orig ? x[(gb * Ssz + t) * Fsz] : spred[b];
            else if (f < 32) v = x[(gb * Ssz + t) * Fsz + f];
            else             v = use_orig ? 0.f : 1.f;
            sA[f * AROWF + b] = v;
        }
        for (int idx = tid; idx < 128 * 33; idx += NTHR) {
            int r = idx / 33, f = idx - r * 33;
            float w = Wih0[((r >> 5) * Hsz + bn + (r & 31)) * 33 + f];
            sW64[f * WROW64 + r] = pack2(w, w);
        }
        loadA(hsrc0, 0); loadW(Whh0, 0);    // prologue for phase 2 (regs only)
        __syncthreads();
        fma_tile<33>(sA64, sW64, mb4, jgc4, acc);

        // phase 2: K = 512 recurrent, register-staged chunks of 32
#pragma unroll 1
        for (int kc = 0; kc < 16; kc++) {
            __syncthreads();
            storeAW();
            __syncthreads();
            if (kc < 15) { loadA(hsrc0, kc + 1); loadW(Whh0, kc + 1); }
            fma_tile<32>(sA64, sW64, mb4, jgc4, acc);
        }
        epilogue(d_bsum0, d_c0, hdst0, acc);
        gsync();

        // ================= layer 1 =================
#pragma unroll
        for (int j = 0; j < 4; j++)
#pragma unroll
            for (int p = 0; p < 4; p++) acc[j][p] = 0ull;

        loadA(hdst0, 0); loadW(Wih1, 0);
#pragma unroll 1
        for (int kc = 0; kc < 32; kc++) {
            __syncthreads();
            storeAW();
            __syncthreads();
            int kn = kc + 1;
            if (kn < 32) {
                if (kn < 16) { loadA(hdst0, kn);      loadW(Wih1, kn); }
                else         { loadA(hsrc1, kn - 16); loadW(Whh1, kn - 16); }
            }
            fma_tile<32>(sA64, sW64, mb4, jgc4, acc);
        }
        epilogue(d_bsum1, d_c1, hdst1, acc);
        gsync();
    }

    // ---- final output column ----
    if (jt == 0) {
        const float* __restrict__ hp1 = d_h1[Ssz & 1];
        int b = tid >> 2;
        int k0 = (tid & 3) * 128;
        float s = 0.f;
#pragma unroll 8
        for (int k = 0; k < 128; k++) s += hp1[(bm + b) * Hsz + k0 + k] * Wout[k0 + k];
        s += __shfl_down_sync(0xffffffffu, s, 2);
        s += __shfl_down_sync(0xffffffffu, s, 1);
        if ((tid & 3) == 0) out[(bm + b) * Ssz + (Ssz - 1)] = s + bout0;
    }
}

// ---------------- launch ------------------------------------------------------
extern "C" void kernel_launch(void* const* d_in, const int* in_sizes, int n_in,
                              void* d_out, int out_size) {
    const float* x    = (const float*)d_in[0];
    const float* Wih0 = (const float*)d_in[1];
    const float* Whh0 = (const float*)d_in[2];
    const float* bih0 = (const float*)d_in[3];
    const float* bhh0 = (const float*)d_in[4];
    const float* Wih1 = (const float*)d_in[5];
    const float* Whh1 = (const float*)d_in[6];
    const float* bih1 = (const float*)d_in[7];
    const float* bhh1 = (const float*)d_in[8];
    const float* Wout = (const float*)d_in[9];
    const float* bout = (const float*)d_in[10];
    float* out = (float*)d_out;

    init_state<<<(Bsz * Hsz + 255) / 256, 256>>>(bih0, bhh0, bih1, bhh1);
    run_all<<<NCTA, NTHR>>>(x, Wih0, Whh0, Wih1, Whh1, Wout, bout, out);
}

// round 7
// speedup vs baseline: 2.4024x; 2.4024x over previous
#include <cuda_runtime.h>
#include <cuda_fp16.h>
#include <cstdint>

typedef unsigned long long u64;
typedef unsigned int u32;

#define Bsz  512
#define Ssz  2688
#define WEEK 672
#define Hsz  512
#define Gm   4
#define Gn   32
#define K0   576          // layer0 K padded: 64 (33 feats + pad) + 512
#define K1   1024
#define NTHR 256

// ---- dynamic smem layout (bytes) ----
#define OFF_WOUT 0        // 512 f32
#define OFF_B0   2048     // 64 f32
#define OFF_B1   2304     // 64 f32
#define OFF_TILE 4096     // 1024-aligned tile stages
#define STAGE_BYTES 49152
#define AHI_OFF(s) (OFF_TILE + (s)*STAGE_BYTES)
#define ALO_OFF(s) (AHI_OFF(s) + 16384)
#define WHI_OFF(s) (AHI_OFF(s) + 32768)
#define WLO_OFF(s) (AHI_OFF(s) + 40960)
#define SMEM_BYTES (OFF_TILE + 2*STAGE_BYTES)   // 102400
#define SGROW 72          // gate-exchange row stride (f32)

// ---------------- persistent device state (no allocation) -------------------
__device__ __half d_W0hi[2048 * K0], d_W0lo[2048 * K0];
__device__ __half d_W1hi[2048 * K1], d_W1lo[2048 * K1];
__device__ __half d_h0hi[2][Bsz * Hsz], d_h0lo[2][Bsz * Hsz];
__device__ __half d_h1hi[2][Bsz * Hsz], d_h1lo[2][Bsz * Hsz];
__device__ float  d_c0[Bsz * Hsz], d_c1[Bsz * Hsz];
__device__ float  d_bs0[2048], d_bs1[2048];      // bias sums, permuted gc' = j*4+g
__device__ float  d_pred[Bsz];
__device__ unsigned d_bar[Gm];

__device__ __forceinline__ float sigm(float v) { return 1.f / (1.f + expf(-v)); }
__device__ __forceinline__ u32 swz(u32 off) { return off ^ ((off >> 3) & 0x70); }

// ---------------- baseline-ISA tensor primitives ----------------------------
__device__ __forceinline__ void ldsm4(u32 a, u32& r0, u32& r1, u32& r2, u32& r3) {
    asm volatile("ldmatrix.sync.aligned.m8n8.x4.shared.b16 {%0,%1,%2,%3}, [%4];"
                 : "=r"(r0), "=r"(r1), "=r"(r2), "=r"(r3) : "r"(a));
}
__device__ __forceinline__ void mma16816(float* d, const u32* a, u32 b0, u32 b1) {
    asm volatile(
        "mma.sync.aligned.m16n8k16.row.col.f32.f16.f16.f32 "
        "{%0,%1,%2,%3}, {%4,%5,%6,%7}, {%8,%9}, {%0,%1,%2,%3};"
        : "+f"(d[0]), "+f"(d[1]), "+f"(d[2]), "+f"(d[3])
        : "r"(a[0]), "r"(a[1]), "r"(a[2]), "r"(a[3]), "r"(b0), "r"(b1));
}
__device__ __forceinline__ void cpa16(u32 dst, const void* src) {
    asm volatile("cp.async.cg.shared.global [%0], [%1], 16;" :: "r"(dst), "l"(src));
}
#define CP_COMMIT() asm volatile("cp.async.commit_group;" ::: "memory")
#define CP_WAIT1()  asm volatile("cp.async.wait_group 1;" ::: "memory")
#define CP_WAIT0()  asm volatile("cp.async.wait_group 0;" ::: "memory")

// ---------------- init: split/permute weights, zero state --------------------
__global__ void init_all(const float* __restrict__ Wih0, const float* __restrict__ Whh0,
                         const float* __restrict__ bih0, const float* __restrict__ bhh0,
                         const float* __restrict__ Wih1, const float* __restrict__ Whh1,
                         const float* __restrict__ bih1, const float* __restrict__ bhh1) {
    long i0 = (long)blockIdx.x * blockDim.x + threadIdx.x;
    long stride = (long)gridDim.x * blockDim.x;
    for (long i = i0; i < 2048L * K0; i += stride) {
        int gc = (int)(i / K0), k = (int)(i % K0);
        int j = gc >> 2, g = gc & 3, row = g * 512 + j;
        float w = 0.f;
        if (k < 33)       w = Wih0[row * 33 + k];
        else if (k >= 64) w = Whh0[row * 512 + (k - 64)];
        __half hi = __float2half_rn(w);
        d_W0hi[i] = hi;
        d_W0lo[i] = __float2half_rn(w - __half2float(hi));
    }
    for (long i = i0; i < 2048L * K1; i += stride) {
        int gc = (int)(i / K1), k = (int)(i % K1);
        int j = gc >> 2, g = gc & 3, row = g * 512 + j;
        float w = (k < 512) ? Wih1[row * 512 + k] : Whh1[row * 512 + (k - 512)];
        __half hi = __float2half_rn(w);
        d_W1hi[i] = hi;
        d_W1lo[i] = __float2half_rn(w - __half2float(hi));
    }
    for (long i = i0; i < 2048; i += stride) {
        int j = (int)(i >> 2), g = (int)(i & 3), row = g * 512 + j;
        d_bs0[i] = bih0[row] + bhh0[row];
        d_bs1[i] = bih1[row] + bhh1[row];
    }
    const __half z = __float2half_rn(0.f);
    for (long i = i0; i < (long)Bsz * Hsz; i += stride) {
        d_h0hi[0][i] = z; d_h0hi[1][i] = z; d_h0lo[0][i] = z; d_h0lo[1][i] = z;
        d_h1hi[0][i] = z; d_h1hi[1][i] = z; d_h1lo[0][i] = z; d_h1lo[1][i] = z;
        d_c0[i] = 0.f;    d_c1[i] = 0.f;
    }
    for (long i = i0; i < Bsz; i += stride) d_pred[i] = 0.f;
    if (i0 < Gm) d_bar[i0] = 0u;
}

// ---------------- the persistent kernel --------------------------------------
__global__ void __launch_bounds__(NTHR, 1) run_all(
    const float* __restrict__ x, const float* __restrict__ Wout,
    const float* __restrict__ bout, float* __restrict__ out) {
    extern __shared__ __align__(16) char smem[];
    const int tid = threadIdx.x, wid = tid >> 5, lane = tid & 31;
    const int n = blockIdx.x, mrow = blockIdx.y;
    const int bm = mrow * 128;
    const u32 sb = (u32)__cvta_generic_to_shared(smem);
    const float bout0 = bout[0];

    const int warp_m = (wid & 1) * 64;
    const int warp_n = (wid >> 1) * 16;
    // ldmatrix per-thread byte offsets (pre-swizzle), A and B tiles (128B rows)
    const u32 aoff_base = (u32)((warp_m + (lane & 7) + ((lane >> 3) & 1) * 8) * 128
                                + (lane >> 4) * 16);
    const u32 boff_base = (u32)((warp_n + (lane & 7) + (lane >> 4) * 8) * 128
                                + ((lane >> 3) & 1) * 16);

    float* sWo = reinterpret_cast<float*>(smem + OFF_WOUT);
    float* sB0 = reinterpret_cast<float*>(smem + OFF_B0);
    float* sB1 = reinterpret_cast<float*>(smem + OFF_B1);
    for (int i = tid; i < 512; i += NTHR) sWo[i] = Wout[i];
    for (int i = tid; i < 64; i += NTHR) {
        sB0[i] = d_bs0[n * 64 + i];
        sB1[i] = d_bs1[n * 64 + i];
    }
    __syncthreads();

    float acc[4][2][4];

    auto stageA = [&](const __half* __restrict__ hi, const __half* __restrict__ lo,
                      int kc, int s) {
#pragma unroll
        for (int q = 0; q < 4; q++) {
            int u = tid + q * NTHR;            // 0..1023
            int r = u >> 3, c8 = u & 7;
            long o = (long)(bm + r) * Hsz + kc + c8 * 8;
            u32 sw = swz((u32)(r * 128 + c8 * 16));
            cpa16(sb + AHI_OFF(s) + sw, hi + o);
            cpa16(sb + ALO_OFF(s) + sw, lo + o);
        }
    };
    auto stageW = [&](const __half* __restrict__ hi, const __half* __restrict__ lo,
                      int Kd, int kc, int s) {
#pragma unroll
        for (int q = 0; q < 2; q++) {
            int u = tid + q * NTHR;            // 0..511
            int r = u >> 3, c8 = u & 7;
            long o = (long)(n * 64 + r) * Kd + kc + c8 * 8;
            u32 sw = swz((u32)(r * 128 + c8 * 16));
            cpa16(sb + WHI_OFF(s) + sw, hi + o);
            cpa16(sb + WLO_OFF(s) + sw, lo + o);
        }
    };
    auto mma_chunk = [&](int s) {
        const u32 ahiB = sb + AHI_OFF(s), aloB = sb + ALO_OFF(s);
        const u32 whiB = sb + WHI_OFF(s), wloB = sb + WLO_OFF(s);
#pragma unroll
        for (int kk = 0; kk < 4; kk++) {
            u32 ah[4][4], al[4][4], bh[4], bl[4];
#pragma unroll
            for (int mf = 0; mf < 4; mf++) {
                u32 sw = swz(aoff_base + mf * 2048 + kk * 32);
                ldsm4(ahiB + sw, ah[mf][0], ah[mf][1], ah[mf][2], ah[mf][3]);
                ldsm4(aloB + sw, al[mf][0], al[mf][1], al[mf][2], al[mf][3]);
            }
            {
                u32 sw = swz(boff_base + kk * 32);
                ldsm4(whiB + sw, bh[0], bh[1], bh[2], bh[3]);
                ldsm4(wloB + sw, bl[0], bl[1], bl[2], bl[3]);
            }
#pragma unroll
            for (int mf = 0; mf < 4; mf++)
#pragma unroll
                for (int nf = 0; nf < 2; nf++) {
                    float* d = &acc[mf][nf][0];
                    mma16816(d, ah[mf], bh[nf * 2], bh[nf * 2 + 1]);  // ahi*whi
                    mma16816(d, al[mf], bh[nf * 2], bh[nf * 2 + 1]);  // alo*whi
                    mma16816(d, ah[mf], bl[nf * 2], bl[nf * 2 + 1]);  // ahi*wlo
                }
        }
    };
    auto epilogue = [&](float* __restrict__ cptr, const float* __restrict__ bs,
                        __half* __restrict__ hhi, __half* __restrict__ hlo) {
        float* sG = reinterpret_cast<float*>(smem + OFF_TILE);  // 128 x SGROW overlay
#pragma unroll
        for (int mf = 0; mf < 4; mf++)
#pragma unroll
            for (int nf = 0; nf < 2; nf++) {
                int m = warp_m + mf * 16 + (lane >> 2);
                int nn = warp_n + nf * 8 + (lane & 3) * 2;
                *reinterpret_cast<float2*>(&sG[m * SGROW + nn]) =
                    make_float2(acc[mf][nf][0], acc[mf][nf][1]);
                *reinterpret_cast<float2*>(&sG[(m + 8) * SGROW + nn]) =
                    make_float2(acc[mf][nf][2], acc[mf][nf][3]);
            }
        __syncthreads();
        int b = tid >> 1, half = tid & 1;
        long hb = (long)(bm + b) * Hsz + n * 16 + half * 8;
        __align__(16) __half hh[8], hl[8];
#pragma unroll
        for (int u = 0; u < 8; u++) {
            int jj = half * 8 + u;
            const float* gp = &sG[b * SGROW + jj * 4];
            float iv = sigm(gp[0] + bs[jj * 4 + 0]);
            float fv = sigm(gp[1] + bs[jj * 4 + 1]);
            float gv = tanhf(gp[2] + bs[jj * 4 + 2]);
            float ov = sigm(gp[3] + bs[jj * 4 + 3]);
            float cn = fv * cptr[hb + u] + iv * gv;
            cptr[hb + u] = cn;
            float h = ov * tanhf(cn);
            hh[u] = __float2half_rn(h);
            hl[u] = __float2half_rn(h - __half2float(hh[u]));
        }
        *reinterpret_cast<uint4*>(hhi + hb) = *reinterpret_cast<uint4*>(hh);
        *reinterpret_cast<uint4*>(hlo + hb) = *reinterpret_cast<uint4*>(hl);
        __syncthreads();
    };
    auto rowsync = [&]() {
        __syncthreads();
        if (tid == 0) {
            unsigned old, cur, one = 1u;
            asm volatile("atom.release.gpu.add.u32 %0, [%1], %2;"
                         : "=r"(old) : "l"(&d_bar[mrow]), "r"(one) : "memory");
            unsigned target = (old / Gn + 1u) * Gn;
            do {
                asm volatile("ld.acquire.gpu.u32 %0, [%1];"
                             : "=r"(cur) : "l"(&d_bar[mrow]) : "memory");
            } while (cur < target);
        }
        __syncthreads();
    };

#pragma unroll 1
    for (int t = 0; t < Ssz; t++) {
        const int slot = t & 1, nslot = slot ^ 1;
        const bool use_orig = (((t / WEEK) & 1) == 0);

        // ===== layer 0: 9 chunks =====
#pragma unroll
        for (int mf = 0; mf < 4; mf++)
#pragma unroll
            for (int nf = 0; nf < 2; nf++)
#pragma unroll
                for (int q = 0; q < 4; q++) acc[mf][nf][q] = 0.f;

        // chunk0 A: features staged by STS (f16 hi/lo, zero-padded k 33..63)
#pragma unroll 1
        for (int i = tid; i < 128 * 64; i += NTHR) {
            int r = i >> 6, k = i & 63;
            float v = 0.f;
            if (k == 0)       v = use_orig ? x[((long)(bm + r) * Ssz + t) * 32]
                                           : d_pred[bm + r];
            else if (k < 32)  v = x[((long)(bm + r) * Ssz + t) * 32 + k];
            else if (k == 32) v = use_orig ? 0.f : 1.f;
            __half hv = __float2half_rn(v);
            __half lv = __float2half_rn(v - __half2float(hv));
            u32 sw = swz((u32)(r * 128 + k * 2));
            *reinterpret_cast<__half*>(smem + AHI_OFF(0) + sw) = hv;
            *reinterpret_cast<__half*>(smem + ALO_OFF(0) + sw) = lv;
        }
        stageW(d_W0hi, d_W0lo, K0, 0, 0);
        CP_COMMIT();
#pragma unroll 1
        for (int c = 0; c < 9; c++) {
            if (c + 1 < 9) {
                stageA(d_h0hi[slot], d_h0lo[slot], c * 64, (c + 1) & 1);
                stageW(d_W0hi, d_W0lo, K0, (c + 1) * 64, (c + 1) & 1);
                CP_COMMIT();
                CP_WAIT1();
            } else CP_WAIT0();
            __syncthreads();
            mma_chunk(c & 1);
            __syncthreads();
        }
        epilogue(d_c0, sB0, d_h0hi[nslot], d_h0lo[nslot]);
        rowsync();

        // ===== layer 1: 16 chunks =====
#pragma unroll
        for (int mf = 0; mf < 4; mf++)
#pragma unroll
            for (int nf = 0; nf < 2; nf++)
#pragma unroll
                for (int q = 0; q < 4; q++) acc[mf][nf][q] = 0.f;

        stageA(d_h0hi[nslot], d_h0lo[nslot], 0, 0);
        stageW(d_W1hi, d_W1lo, K1, 0, 0);
        CP_COMMIT();
#pragma unroll 1
        for (int c = 0; c < 16; c++) {
            if (c + 1 < 16) {
                int cc = c + 1;
                if (cc < 8) stageA(d_h0hi[nslot], d_h0lo[nslot], cc * 64, cc & 1);
                else        stageA(d_h1hi[slot],  d_h1lo[slot], (cc - 8) * 64, cc & 1);
                stageW(d_W1hi, d_W1lo, K1, cc * 64, cc & 1);
                CP_COMMIT();
                CP_WAIT1();
            } else CP_WAIT0();
            __syncthreads();
            mma_chunk(c & 1);
            __syncthreads();
        }
        epilogue(d_c1, sB1, d_h1hi[nslot], d_h1lo[nslot]);
        rowsync();

        // ===== output projection (n-CTA 0 of each row) =====
        if (n == 0) {
            int r = tid >> 1, hf = tid & 1;
            const __half2* ph2 = reinterpret_cast<const __half2*>(
                &d_h1hi[nslot][(long)(bm + r) * Hsz + hf * 256]);
            const __half2* pl2 = reinterpret_cast<const __half2*>(
                &d_h1lo[nslot][(long)(bm + r) * Hsz + hf * 256]);
            float sacc = 0.f;
#pragma unroll 16
            for (int i = 0; i < 128; i++) {
                float2 a = __half22float2(ph2[i]);
                float2 b = __half22float2(pl2[i]);
                sacc += (a.x + b.x) * sWo[hf * 256 + 2 * i]
                      + (a.y + b.y) * sWo[hf * 256 + 2 * i + 1];
            }
            sacc += __shfl_xor_sync(0xffffffffu, sacc, 1);
            if (hf == 0) {
                float val = sacc + bout0;
                d_pred[bm + r] = val;
                out[(long)(bm + r) * Ssz + t] = val;
            }
        }
        // barrier only when step t+1 consumes predictions
        if ((t + 1 < Ssz) && ((((t + 1) / WEEK) & 1) == 1)) rowsync();
    }
}

// ---------------- launch ------------------------------------------------------
extern "C" void kernel_launch(void* const* d_in, const int* in_sizes, int n_in,
                              void* d_out, int out_size) {
    const float* x    = (const float*)d_in[0];
    const float* Wih0 = (const float*)d_in[1];
    const float* Whh0 = (const float*)d_in[2];
    const float* bih0 = (const float*)d_in[3];
    const float* bhh0 = (const float*)d_in[4];
    const float* Wih1 = (const float*)d_in[5];
    const float* Whh1 = (const float*)d_in[6];
    const float* bih1 = (const float*)d_in[7];
    const float* bhh1 = (const float*)d_in[8];
    const float* Wout = (const float*)d_in[9];
    const float* bout = (const float*)d_in[10];
    float* out = (float*)d_out;

    cudaFuncSetAttribute(run_all, cudaFuncAttributeMaxDynamicSharedMemorySize, SMEM_BYTES);
    init_all<<<1024, 256>>>(Wih0, Whh0, bih0, bhh0, Wih1, Whh1, bih1, bhh1);
    run_all<<<dim3(Gn, Gm), NTHR, SMEM_BYTES>>>(x, Wout, bout, out);
}

// round 8
// speedup vs baseline: 4.1860x; 1.7424x over previous
#include <cuda_runtime.h>
#include <cuda_fp16.h>
#include <cstdint>

typedef unsigned long long u64;
typedef unsigned int u32;

#define Bsz  512
#define Ssz  2688
#define WEEK 672
#define Hsz  512
#define Gm   4
#define Gn   32
#define K0   576
#define K1   1024
#define NTHR 256

// ---- dynamic smem layout (bytes) ----
#define OFF_WOUT  0         // 512 f32
#define OFF_B0    2048      // 64 f32
#define OFF_B1    2304      // 64 f32
#define OFF_FEATA 4096      // 128x64 f16 (16KB), cols>=33 stay zero
#define OFF_FEATW 20480     // 64x64 f16 hi (8KB) + lo (8KB)
#define OFF_TILE  36864     // two 64KB stages
#define ST_A(s)   (OFF_TILE + (s)*65536)            // 2 x 16KB A sub-tiles
#define ST_W(s)   (ST_A(s) + 32768)                 // hi: 2x8KB, lo: 2x8KB
#define SMEM_BYTES (OFF_TILE + 2*65536)             // 167936
#define SGROW 72            // gate-exchange row stride (f32)

// ---------------- persistent device state (no allocation) -------------------
__device__ __half d_W0hi[2048 * K0], d_W0lo[2048 * K0];
__device__ __half d_W1hi[2048 * K1], d_W1lo[2048 * K1];
__device__ __half d_h0[2][Bsz * Hsz], d_h1[2][Bsz * Hsz];
__device__ float  d_c0[Bsz * Hsz], d_c1[Bsz * Hsz];
__device__ float  d_bs0[2048], d_bs1[2048];         // permuted gc' = j*4+g
__device__ float  d_pred[Bsz];
__device__ unsigned d_bar[Gm];

__device__ __forceinline__ float sigm(float v) { return 1.f / (1.f + expf(-v)); }
__device__ __forceinline__ u32 swz(u32 off) { return off ^ ((off >> 3) & 0x70); }

// ---------------- baseline-ISA tensor primitives ----------------------------
__device__ __forceinline__ void ldsm4(u32 a, u32& r0, u32& r1, u32& r2, u32& r3) {
    asm volatile("ldmatrix.sync.aligned.m8n8.x4.shared.b16 {%0,%1,%2,%3}, [%4];"
                 : "=r"(r0), "=r"(r1), "=r"(r2), "=r"(r3) : "r"(a));
}
__device__ __forceinline__ void mma16816(float* d, const u32* a, u32 b0, u32 b1) {
    asm volatile(
        "mma.sync.aligned.m16n8k16.row.col.f32.f16.f16.f32 "
        "{%0,%1,%2,%3}, {%4,%5,%6,%7}, {%8,%9}, {%0,%1,%2,%3};"
        : "+f"(d[0]), "+f"(d[1]), "+f"(d[2]), "+f"(d[3])
        : "r"(a[0]), "r"(a[1]), "r"(a[2]), "r"(a[3]), "r"(b0), "r"(b1));
}
__device__ __forceinline__ void cpa16(u32 dst, const void* src) {
    asm volatile("cp.async.cg.shared.global [%0], [%1], 16;" :: "r"(dst), "l"(src));
}
#define CP_COMMIT() asm volatile("cp.async.commit_group;" ::: "memory")
#define CP_WAIT1()  asm volatile("cp.async.wait_group 1;" ::: "memory")
#define CP_WAIT0()  asm volatile("cp.async.wait_group 0;" ::: "memory")

// ---------------- init: split/permute weights, zero state --------------------
__global__ void init_all(const float* __restrict__ Wih0, const float* __restrict__ Whh0,
                         const float* __restrict__ bih0, const float* __restrict__ bhh0,
                         const float* __restrict__ Wih1, const float* __restrict__ Whh1,
                         const float* __restrict__ bih1, const float* __restrict__ bhh1) {
    long i0 = (long)blockIdx.x * blockDim.x + threadIdx.x;
    long stride = (long)gridDim.x * blockDim.x;
    for (long i = i0; i < 2048L * K0; i += stride) {
        int gc = (int)(i / K0), k = (int)(i % K0);
        int j = gc >> 2, g = gc & 3, row = g * 512 + j;
        float w = 0.f;
        if (k < 33)       w = Wih0[row * 33 + k];
        else if (k >= 64) w = Whh0[row * 512 + (k - 64)];
        __half hi = __float2half_rn(w);
        d_W0hi[i] = hi;
        d_W0lo[i] = __float2half_rn(w - __half2float(hi));
    }
    for (long i = i0; i < 2048L * K1; i += stride) {
        int gc = (int)(i / K1), k = (int)(i % K1);
        int j = gc >> 2, g = gc & 3, row = g * 512 + j;
        float w = (k < 512) ? Wih1[row * 512 + k] : Whh1[row * 512 + (k - 512)];
        __half hi = __float2half_rn(w);
        d_W1hi[i] = hi;
        d_W1lo[i] = __float2half_rn(w - __half2float(hi));
    }
    for (long i = i0; i < 2048; i += stride) {
        int j = (int)(i >> 2), g = (int)(i & 3), row = g * 512 + j;
        d_bs0[i] = bih0[row] + bhh0[row];
        d_bs1[i] = bih1[row] + bhh1[row];
    }
    const __half z = __float2half_rn(0.f);
    for (long i = i0; i < (long)Bsz * Hsz; i += stride) {
        d_h0[0][i] = z; d_h0[1][i] = z; d_h1[0][i] = z; d_h1[1][i] = z;
        d_c0[i] = 0.f;  d_c1[i] = 0.f;
    }
    for (long i = i0; i < Bsz; i += stride) d_pred[i] = 0.f;
    if (i0 < Gm) d_bar[i0] = 0u;
}

// ---------------- the persistent kernel --------------------------------------
__global__ void __launch_bounds__(NTHR, 1) run_all(
    const float* __restrict__ x, const float* __restrict__ Wout,
    const float* __restrict__ bout, float* __restrict__ out) {
    extern __shared__ __align__(16) char smem[];
    const int tid = threadIdx.x, wid = tid >> 5, lane = tid & 31;
    const int n = blockIdx.x, mrow = blockIdx.y;
    const int bm = mrow * 128;
    const u32 sb = (u32)__cvta_generic_to_shared(smem);
    const float bout0 = bout[0];

    const int warp_m = (wid & 1) * 64;
    const int warp_n = (wid >> 1) * 16;
    const u32 aoff_base = (u32)((warp_m + (lane & 7) + ((lane >> 3) & 1) * 8) * 128
                                + (lane >> 4) * 16);
    const u32 boff_base = (u32)((warp_n + (lane & 7) + (lane >> 4) * 8) * 128
                                + ((lane >> 3) & 1) * 16);

    float* sWo = reinterpret_cast<float*>(smem + OFF_WOUT);
    float* sB0 = reinterpret_cast<float*>(smem + OFF_B0);
    float* sB1 = reinterpret_cast<float*>(smem + OFF_B1);
    for (int i = tid; i < 512; i += NTHR) sWo[i] = Wout[i];
    for (int i = tid; i < 64; i += NTHR) {
        sB0[i] = d_bs0[n * 64 + i];
        sB1[i] = d_bs1[n * 64 + i];
    }
    // zero featA (cols >= 33 stay zero forever)
    for (int i = tid; i < 1024; i += NTHR)
        reinterpret_cast<uint4*>(smem + OFF_FEATA)[i] = make_uint4(0, 0, 0, 0);
    // stage constant featW once (64 k-rows x 64 gc, hi+lo)
#pragma unroll
    for (int q = 0; q < 4; q++) {
        int u = tid + q * NTHR;              // 0..1023
        int hl = u >> 9, w = u & 511;
        int r = w >> 3, c8 = w & 7;
        const __half* srcp = hl ? d_W0lo : d_W0hi;
        long o = (long)(n * 64 + r) * K0 + c8 * 8;
        cpa16(sb + OFF_FEATW + hl * 8192 + swz((u32)(r * 128 + c8 * 16)), srcp + o);
    }
    CP_COMMIT(); CP_WAIT0();
    __syncthreads();

    float acc[4][2][4];

    auto stageA = [&](const __half* __restrict__ src, int kc, int s) {
#pragma unroll
        for (int q = 0; q < 8; q++) {
            int u = tid + q * NTHR;          // 0..2047
            int r = u >> 4, c8 = u & 15;
            int tile = c8 >> 3, cc = c8 & 7;
            long o = (long)(bm + r) * Hsz + kc + c8 * 8;
            cpa16(sb + ST_A(s) + tile * 16384 + swz((u32)(r * 128 + cc * 16)), src + o);
        }
    };
    auto stageW = [&](const __half* __restrict__ hi, const __half* __restrict__ lo,
                      int Kd, int kc, int s) {
#pragma unroll
        for (int q = 0; q < 8; q++) {
            int u = tid + q * NTHR;          // 0..2047
            int hl = u >> 10, w = u & 1023;
            int r = w >> 4, c8 = w & 15;     // r 0..63
            int tile = c8 >> 3, cc = c8 & 7;
            const __half* srcp = hl ? lo : hi;
            long o = (long)(n * 64 + r) * Kd + kc + c8 * 8;
            cpa16(sb + ST_W(s) + hl * 16384 + tile * 8192 + swz((u32)(r * 128 + cc * 16)),
                  srcp + o);
        }
    };
    auto mma_chunk = [&](int s) {
        const u32 aB = sb + ST_A(s), wB = sb + ST_W(s);
#pragma unroll
        for (int kk = 0; kk < 8; kk++) {
            int tile = kk >> 2, kkl = kk & 3;
            u32 a_t = aB + tile * 16384, w_t = wB + tile * 8192;
            u32 ah[4][4], bh[4], bl[4];
#pragma unroll
            for (int mf = 0; mf < 4; mf++) {
                u32 sw = swz(aoff_base + mf * 2048 + kkl * 32);
                ldsm4(a_t + sw, ah[mf][0], ah[mf][1], ah[mf][2], ah[mf][3]);
            }
            u32 swb = swz(boff_base + kkl * 32);
            ldsm4(w_t + swb, bh[0], bh[1], bh[2], bh[3]);
            ldsm4(w_t + 16384 + swb, bl[0], bl[1], bl[2], bl[3]);
#pragma unroll
            for (int mf = 0; mf < 4; mf++)
#pragma unroll
                for (int nf = 0; nf < 2; nf++) {
                    float* d = &acc[mf][nf][0];
                    mma16816(d, ah[mf], bh[nf * 2], bh[nf * 2 + 1]);
                    mma16816(d, ah[mf], bl[nf * 2], bl[nf * 2 + 1]);
                }
        }
    };
    auto mma_feat = [&]() {
        const u32 aB = sb + OFF_FEATA, wB = sb + OFF_FEATW;
#pragma unroll
        for (int kk = 0; kk < 4; kk++) {
            u32 ah[4][4], bh[4], bl[4];
#pragma unroll
            for (int mf = 0; mf < 4; mf++) {
                u32 sw = swz(aoff_base + mf * 2048 + kk * 32);
                ldsm4(aB + sw, ah[mf][0], ah[mf][1], ah[mf][2], ah[mf][3]);
            }
            u32 swb = swz(boff_base + kk * 32);
            ldsm4(wB + swb, bh[0], bh[1], bh[2], bh[3]);
            ldsm4(wB + 8192 + swb, bl[0], bl[1], bl[2], bl[3]);
#pragma unroll
            for (int mf = 0; mf < 4; mf++)
#pragma unroll
                for (int nf = 0; nf < 2; nf++) {
                    float* d = &acc[mf][nf][0];
                    mma16816(d, ah[mf], bh[nf * 2], bh[nf * 2 + 1]);
                    mma16816(d, ah[mf], bl[nf * 2], bl[nf * 2 + 1]);
                }
        }
    };
    auto epilogue = [&](float* __restrict__ cptr, const float* __restrict__ bs,
                        __half* __restrict__ hdst) {
        float* sG = reinterpret_cast<float*>(smem + OFF_TILE);
#pragma unroll
        for (int mf = 0; mf < 4; mf++)
#pragma unroll
            for (int nf = 0; nf < 2; nf++) {
                int m = warp_m + mf * 16 + (lane >> 2);
                int nn = warp_n + nf * 8 + (lane & 3) * 2;
                *reinterpret_cast<float2*>(&sG[m * SGROW + nn]) =
                    make_float2(acc[mf][nf][0], acc[mf][nf][1]);
                *reinterpret_cast<float2*>(&sG[(m + 8) * SGROW + nn]) =
                    make_float2(acc[mf][nf][2], acc[mf][nf][3]);
            }
        __syncthreads();
        int b = tid >> 1, half = tid & 1;
        long hb = (long)(bm + b) * Hsz + n * 16 + half * 8;
        __align__(16) __half hh[8];
#pragma unroll
        for (int u = 0; u < 8; u++) {
            int jj = half * 8 + u;
            const float* gp = &sG[b * SGROW + jj * 4];
            float iv = sigm(gp[0] + bs[jj * 4 + 0]);
            float fv = sigm(gp[1] + bs[jj * 4 + 1]);
            float gv = tanhf(gp[2] + bs[jj * 4 + 2]);
            float ov = sigm(gp[3] + bs[jj * 4 + 3]);
            float cn = fv * cptr[hb + u] + iv * gv;
            cptr[hb + u] = cn;
            hh[u] = __float2half_rn(ov * tanhf(cn));
        }
        *reinterpret_cast<uint4*>(hdst + hb) = *reinterpret_cast<uint4*>(hh);
        __syncthreads();
    };
    auto rowsync = [&]() {
        __syncthreads();
        if (tid == 0) {
            unsigned old, cur, one = 1u;
            asm volatile("atom.release.gpu.add.u32 %0, [%1], %2;"
                         : "=r"(old) : "l"(&d_bar[mrow]), "r"(one) : "memory");
            unsigned target = (old / Gn + 1u) * Gn;
            do {
                asm volatile("ld.acquire.gpu.u32 %0, [%1];"
                             : "=r"(cur) : "l"(&d_bar[mrow]) : "memory");
            } while (cur < target);
        }
        __syncthreads();
    };

#pragma unroll 1
    for (int t = 0; t < Ssz; t++) {
        const int slot = t & 1, nslot = slot ^ 1;
        const bool use_orig = (((t / WEEK) & 1) == 0);
        const __half* h0s = d_h0[slot];
        __half* h0d = d_h0[nslot];
        const __half* h1s = d_h1[slot];
        __half* h1d = d_h1[nslot];

        // ---- stage features into featA (cols 0..32; rest stays zero) ----
        {
            int r = tid >> 1, hf = tid & 1;
            const float* xr = &x[((long)(bm + r) * Ssz + t) * 32];
            char* fa = smem + OFF_FEATA;
            if (hf == 0) {
                float f0 = use_orig ? xr[0] : d_pred[bm + r];
                *reinterpret_cast<__half*>(fa + swz((u32)(r * 128))) = __float2half_rn(f0);
#pragma unroll
                for (int f = 1; f < 16; f++)
                    *reinterpret_cast<__half*>(fa + swz((u32)(r * 128 + f * 2))) =
                        __float2half_rn(xr[f]);
            } else {
#pragma unroll
                for (int f = 16; f < 32; f++)
                    *reinterpret_cast<__half*>(fa + swz((u32)(r * 128 + f * 2))) =
                        __float2half_rn(xr[f]);
                *reinterpret_cast<__half*>(fa + swz((u32)(r * 128 + 64))) =
                    __float2half_rn(use_orig ? 0.f : 1.f);
            }
        }

        // ================= layer 0: feat (K=64) + 4 chunks (K=128) =================
        stageA(h0s, 0, 0);   stageW(d_W0hi, d_W0lo, K0, 64, 0);  CP_COMMIT();
        stageA(h0s, 128, 1); stageW(d_W0hi, d_W0lo, K0, 192, 1); CP_COMMIT();
        __syncthreads();     // featA visible
#pragma unroll
        for (int mf = 0; mf < 4; mf++)
#pragma unroll
            for (int nf = 0; nf < 2; nf++)
#pragma unroll
                for (int q = 0; q < 4; q++) acc[mf][nf][q] = 0.f;
        mma_feat();          // overlaps with in-flight cp.async
#pragma unroll 1
        for (int c = 0; c < 4; c++) {
            if (c == 3) CP_WAIT0(); else CP_WAIT1();
            __syncthreads();
            mma_chunk(c & 1);
            __syncthreads();
            if (c + 2 < 4) {
                stageA(h0s, (c + 2) * 128, c & 1);
                stageW(d_W0hi, d_W0lo, K0, 64 + (c + 2) * 128, c & 1);
                CP_COMMIT();
            }
        }
        epilogue(d_c0, sB0, h0d);
        rowsync();

        // ================= layer 1: 8 chunks (K=128) =================
        stageA(h0d, 0, 0);   stageW(d_W1hi, d_W1lo, K1, 0, 0);   CP_COMMIT();
        stageA(h0d, 128, 1); stageW(d_W1hi, d_W1lo, K1, 128, 1); CP_COMMIT();
#pragma unroll
        for (int mf = 0; mf < 4; mf++)
#pragma unroll
            for (int nf = 0; nf < 2; nf++)
#pragma unroll
                for (int q = 0; q < 4; q++) acc[mf][nf][q] = 0.f;
#pragma unroll 1
        for (int c = 0; c < 8; c++) {
            if (c == 7) CP_WAIT0(); else CP_WAIT1();
            __syncthreads();
            mma_chunk(c & 1);
            __syncthreads();
            if (c + 2 < 8) {
                int cc = c + 2;
                const __half* asrc = (cc < 4) ? h0d : h1s;
                stageA(asrc, (cc & 3) * 128, c & 1);
                stageW(d_W1hi, d_W1lo, K1, cc * 128, c & 1);
                CP_COMMIT();
            }
        }
        epilogue(d_c1, sB1, h1d);
        rowsync();

        // ================= output projection (n-CTA 0 of each row) =================
        if (n == 0) {
            int r = tid >> 1, hf = tid & 1;
            const __half2* ph2 = reinterpret_cast<const __half2*>(
                &h1d[(long)(bm + r) * Hsz + hf * 256]);
            float sacc = 0.f;
#pragma unroll 16
            for (int i = 0; i < 128; i++) {
                float2 a = __half22float2(ph2[i]);
                sacc += a.x * sWo[hf * 256 + 2 * i] + a.y * sWo[hf * 256 + 2 * i + 1];
            }
            sacc += __shfl_xor_sync(0xffffffffu, sacc, 1);
            if (hf == 0) {
                float val = sacc + bout0;
                d_pred[bm + r] = val;
                out[(long)(bm + r) * Ssz + t] = val;
            }
        }
        if ((t + 1 < Ssz) && ((((t + 1) / WEEK) & 1) == 1)) rowsync();
    }
}

// ---------------- launch ------------------------------------------------------
extern "C" void kernel_launch(void* const* d_in, const int* in_sizes, int n_in,
                              void* d_out, int out_size) {
    const float* x    = (const float*)d_in[0];
    const float* Wih0 = (const float*)d_in[1];
    const float* Whh0 = (const float*)d_in[2];
    const float* bih0 = (const float*)d_in[3];
    const float* bhh0 = (const float*)d_in[4];
    const float* Wih1 = (const float*)d_in[5];
    const float* Whh1 = (const float*)d_in[6];
    const float* bih1 = (const float*)d_in[7];
    const float* bhh1 = (const float*)d_in[8];
    const float* Wout = (const float*)d_in[9];
    const float* bout = (const float*)d_in[10];
    float* out = (float*)d_out;

    cudaFuncSetAttribute(run_all, cudaFuncAttributeMaxDynamicSharedMemorySize, SMEM_BYTES);
    init_all<<<1024, 256>>>(Wih0, Whh0, bih0, bhh0, Wih1, Whh1, bih1, bhh1);
    run_all<<<dim3(Gn, Gm), NTHR, SMEM_BYTES>>>(x, Wout, bout, out);
}

// round 9
// speedup vs baseline: 6.0303x; 1.4406x over previous
#include <cuda_runtime.h>
#include <cuda_fp16.h>

typedef unsigned long long u64;
typedef unsigned int u32;

#define Bsz  512
#define Ssz  2688
#define WEEK 672
#define Hsz  512
#define Gn   64
#define Gm   2
#define NTHR 256
#define K0   576
#define K1   1024

// ---- smem layout (bytes) ----
#define OFF_W0R   0           // 9 tiles x 4KB  = 36864
#define OFF_W1R   36864       // 16 tiles x 4KB = 65536
#define OFF_A     102400      // 3 stages x 32768 = 98304
#define OFF_WOUT  200704      // 512 f32 = 2048
#define OFF_SPRED 202752      // 256 f32 = 1024
#define SMEM_BYTES 203776

// ---------------- persistent device state (no allocation) -------------------
__device__ __half d_W0f[2048 * K0];
__device__ __half d_W1f[2048 * K1];
__device__ __half d_h0[2][Bsz * Hsz];
__device__ __half d_h1[2][Bsz * Hsz];
__device__ float  d_bs0[2048], d_bs1[2048];     // permuted gc' = j*4+g
__device__ unsigned d_barA[Gm], d_barB[Gm];

__device__ __forceinline__ u32 swz(u32 off) { return off ^ ((off >> 3) & 0x70); }
__device__ __forceinline__ float fsig(float x) {
    return __fdividef(1.f, 1.f + __expf(-x));
}
__device__ __forceinline__ float ftanh(float x) {
    float e = __expf(-2.f * x);
    return __fdividef(1.f - e, 1.f + e);
}

// ---------------- baseline-ISA primitives ------------------------------------
__device__ __forceinline__ void ldsm4(u32 a, u32& r0, u32& r1, u32& r2, u32& r3) {
    asm volatile("ldmatrix.sync.aligned.m8n8.x4.shared.b16 {%0,%1,%2,%3}, [%4];"
                 : "=r"(r0), "=r"(r1), "=r"(r2), "=r"(r3) : "r"(a));
}
__device__ __forceinline__ void mma16816(float* d, const u32* a, u32 b0, u32 b1) {
    asm volatile(
        "mma.sync.aligned.m16n8k16.row.col.f32.f16.f16.f32 "
        "{%0,%1,%2,%3}, {%4,%5,%6,%7}, {%8,%9}, {%0,%1,%2,%3};"
        : "+f"(d[0]), "+f"(d[1]), "+f"(d[2]), "+f"(d[3])
        : "r"(a[0]), "r"(a[1]), "r"(a[2]), "r"(a[3]), "r"(b0), "r"(b1));
}
__device__ __forceinline__ void cpa16(u32 dst, const void* src) {
    asm volatile("cp.async.cg.shared.global [%0], [%1], 16;" :: "r"(dst), "l"(src));
}
#define CP_COMMIT() asm volatile("cp.async.commit_group;" ::: "memory")
#define CP_WAIT1()  asm volatile("cp.async.wait_group 1;" ::: "memory")
#define CP_WAIT0()  asm volatile("cp.async.wait_group 0;" ::: "memory")

// ---------------- init --------------------------------------------------------
__global__ void init_all(const float* __restrict__ Wih0, const float* __restrict__ Whh0,
                         const float* __restrict__ bih0, const float* __restrict__ bhh0,
                         const float* __restrict__ Wih1, const float* __restrict__ Whh1,
                         const float* __restrict__ bih1, const float* __restrict__ bhh1) {
    long i0 = (long)blockIdx.x * blockDim.x + threadIdx.x;
    long stride = (long)gridDim.x * blockDim.x;
    for (long i = i0; i < 2048L * K0; i += stride) {
        int gc = (int)(i / K0), k = (int)(i % K0);
        int j = gc >> 2, g = gc & 3, row = g * 512 + j;
        float w = 0.f;
        if (k < 33)       w = Wih0[row * 33 + k];
        else if (k >= 64) w = Whh0[row * 512 + (k - 64)];
        d_W0f[i] = __float2half_rn(w);
    }
    for (long i = i0; i < 2048L * K1; i += stride) {
        int gc = (int)(i / K1), k = (int)(i % K1);
        int j = gc >> 2, g = gc & 3, row = g * 512 + j;
        float w = (k < 512) ? Wih1[row * 512 + k] : Whh1[row * 512 + (k - 512)];
        d_W1f[i] = __float2half_rn(w);
    }
    for (long i = i0; i < 2048; i += stride) {
        int j = (int)(i >> 2), g = (int)(i & 3), row = g * 512 + j;
        d_bs0[i] = bih0[row] + bhh0[row];
        d_bs1[i] = bih1[row] + bhh1[row];
    }
    const __half z = __float2half_rn(0.f);
    for (long i = i0; i < (long)Bsz * Hsz; i += stride) {
        d_h0[0][i] = z; d_h0[1][i] = z; d_h1[0][i] = z; d_h1[1][i] = z;
    }
    if (i0 < Gm) { d_barA[i0] = 0u; d_barB[i0] = 0u; }
}

// ---------------- the persistent kernel --------------------------------------
__global__ void __launch_bounds__(NTHR, 1) run_all(
    const float* __restrict__ x, const float* __restrict__ Wout,
    const float* __restrict__ bout, float* __restrict__ out) {
    extern __shared__ __align__(128) char smem[];
    const int tid = threadIdx.x, wid = tid >> 5, lane = tid & 31;
    const int n = blockIdx.x, mrow = blockIdx.y;
    const int bm = mrow * 256;
    const u32 sb = (u32)__cvta_generic_to_shared(smem);
    const float bout0 = bout[0];

    const int warp_m = (wid >> 1) * 64;
    const int warp_n = (wid & 1) * 16;
    const u32 aoff_base = (u32)((warp_m + (lane & 7) + ((lane >> 3) & 1) * 8) * 128
                                + (lane >> 4) * 16);
    const u32 boff_base = (u32)((warp_n + (lane & 7) + (lane >> 4) * 8) * 128
                                + ((lane >> 3) & 1) * 16);
    const int jl0 = (warp_n >> 2) + ((lane & 3) >> 1);    // nf=0 local j
    // bias registers (constant per thread): [nf] -> (i,f,g,o)
    float4 bia0[2], bia1[2];
    bia0[0] = *reinterpret_cast<const float4*>(&d_bs0[n * 32 + jl0 * 4]);
    bia0[1] = *reinterpret_cast<const float4*>(&d_bs0[n * 32 + (jl0 + 2) * 4]);
    bia1[0] = *reinterpret_cast<const float4*>(&d_bs1[n * 32 + jl0 * 4]);
    bia1[1] = *reinterpret_cast<const float4*>(&d_bs1[n * 32 + (jl0 + 2) * 4]);

    float* sWo = reinterpret_cast<float*>(smem + OFF_WOUT);
    float* sPred = reinterpret_cast<float*>(smem + OFF_SPRED);
    for (int i = tid; i < 512; i += NTHR) sWo[i] = Wout[i];

    // ---- load resident weights (once) ----
#pragma unroll
    for (int q = 0; q < 9; q++) {
        int u = tid + q * NTHR;                 // 0..2303
        int tile = u >> 8, rr = (u & 255) >> 3, c8 = u & 7;
        cpa16(sb + OFF_W0R + tile * 4096 + swz((u32)(rr * 128 + c8 * 16)),
              d_W0f + (long)(n * 32 + rr) * K0 + tile * 64 + c8 * 8);
    }
#pragma unroll
    for (int q = 0; q < 16; q++) {
        int u = tid + q * NTHR;                 // 0..4095
        int tile = u >> 8, rr = (u & 255) >> 3, c8 = u & 7;
        cpa16(sb + OFF_W1R + tile * 4096 + swz((u32)(rr * 128 + c8 * 16)),
              d_W1f + (long)(n * 32 + rr) * K1 + tile * 64 + c8 * 8);
    }
    CP_COMMIT(); CP_WAIT0();
    __syncthreads();

    float acc[4][2][4];
    float c0r[4][2], c1r[4][2];
#pragma unroll
    for (int mf = 0; mf < 4; mf++)
#pragma unroll
        for (int nf = 0; nf < 2; nf++) { c0r[mf][nf] = 0.f; c1r[mf][nf] = 0.f; }

    auto stageA = [&](int g, int tt, int s) {
        const __half* src;
        int kc;
        if (g <= 8)       { src = d_h0[tt & 1];       kc = (g - 1) * 64; }
        else if (g <= 16) { src = d_h1[tt & 1];       kc = (g - 9) * 64; }
        else              { src = d_h0[(tt & 1) ^ 1]; kc = (g - 17) * 64; }
        u32 base = sb + OFF_A + s * 32768;
#pragma unroll
        for (int q = 0; q < 8; q++) {
            int u = tid + q * NTHR;
            int r = u >> 3, c8 = u & 7;
            cpa16(base + swz((u32)(r * 128 + c8 * 16)),
                  src + (long)(bm + r) * Hsz + kc + c8 * 8);
        }
        CP_COMMIT();
    };
    auto mma_tiles = [&](u32 aB, u32 wB) {
#pragma unroll
        for (int kkl = 0; kkl < 4; kkl++) {
            u32 ah[4][4], bh[4];
#pragma unroll
            for (int mf = 0; mf < 4; mf++)
                ldsm4(aB + swz(aoff_base + mf * 2048 + kkl * 32),
                      ah[mf][0], ah[mf][1], ah[mf][2], ah[mf][3]);
            ldsm4(wB + swz(boff_base + kkl * 32), bh[0], bh[1], bh[2], bh[3]);
#pragma unroll
            for (int mf = 0; mf < 4; mf++)
#pragma unroll
                for (int nf = 0; nf < 2; nf++)
                    mma16816(&acc[mf][nf][0], ah[mf], bh[nf * 2], bh[nf * 2 + 1]);
        }
    };
    auto epilogue = [&](float cre[4][2], const float4* bia, __half* __restrict__ hdst) {
        const bool od = (lane & 1);
        const int rbase = warp_m + (lane >> 2) + (od ? 8 : 0);
#pragma unroll
        for (int mf = 0; mf < 4; mf++)
#pragma unroll
            for (int nf = 0; nf < 2; nf++) {
                float d0 = acc[mf][nf][0], d1 = acc[mf][nf][1];
                float d2 = acc[mf][nf][2], d3 = acc[mf][nf][3];
                float v1 = __shfl_xor_sync(0xffffffffu, od ? d0 : d2, 1);
                float v2 = __shfl_xor_sync(0xffffffffu, od ? d1 : d3, 1);
                float gi = od ? v1 : d0;
                float gf = od ? v2 : d1;
                float gg = od ? d2 : v1;
                float go = od ? d3 : v2;
                float iv = fsig(gi + bia[nf].x);
                float fv = fsig(gf + bia[nf].y);
                float gv = ftanh(gg + bia[nf].z);
                float ov = fsig(go + bia[nf].w);
                float cn = fv * cre[mf][nf] + iv * gv;
                cre[mf][nf] = cn;
                int row = rbase + mf * 16;
                int col = n * 8 + jl0 + nf * 2;
                hdst[(long)(bm + row) * Hsz + col] = __float2half_rn(ov * ftanh(cn));
            }
    };
    auto barwait = [&](unsigned* ctr, unsigned target) {
        if (tid == 0) {
            unsigned cur;
            do {
                asm volatile("ld.acquire.gpu.u32 %0, [%1];"
                             : "=r"(cur) : "l"(ctr) : "memory");
            } while (cur < target);
        }
        __syncthreads();
    };
    auto arrive = [&](unsigned* ctr) {
        __syncthreads();
        if (tid == 0) {
            unsigned old, one = 1u;
            asm volatile("atom.release.gpu.add.u32 %0, [%1], %2;"
                         : "=r"(old) : "l"(ctr), "r"(one) : "memory");
        }
    };

    // prologue: stage chunks 1,2 of step 0
    stageA(1, 0, (1 + 0) % 3);
    stageA(2, 0, (2 + 0) % 3);

#pragma unroll 1
    for (int t = 0; t < Ssz; t++) {
        const bool fb = (((t / WEEK) & 1) == 1);      // use predictions this step
        const __half* h1s = d_h1[t & 1];
        __half* h0d = d_h0[(t & 1) ^ 1];
        __half* h1d = d_h1[(t & 1) ^ 1];

#pragma unroll 1
        for (int g = 0; g < 25; g++) {
            const int s = (g + t) % 3;
            const u32 aB = sb + OFF_A + s * 32768;

            if (g == 0) {
                if (fb) {
                    barwait(&d_barB[mrow], 64u * (u32)t);
                    // local full out-projection for all 256 rows (also writes out)
                    const uint4* hp = reinterpret_cast<const uint4*>(
                        h1s + (long)(bm + tid) * Hsz);
                    float sv = 0.f;
#pragma unroll 8
                    for (int i = 0; i < 64; i++) {
                        uint4 vv = hp[i];
                        const __half2* pp = reinterpret_cast<const __half2*>(&vv);
#pragma unroll
                        for (int q = 0; q < 4; q++) {
                            float2 f2 = __half22float2(pp[q]);
                            sv += f2.x * sWo[i * 8 + q * 2] + f2.y * sWo[i * 8 + q * 2 + 1];
                        }
                    }
                    sv += bout0;
                    sPred[tid] = sv;
                    if ((tid >> 2) == n) out[(long)(bm + tid) * Ssz + (t - 1)] = sv;
                    __syncthreads();
                }
                // stage features into A stage s (STS)
#pragma unroll
                for (int q = 0; q < 8; q++) {
                    int u = tid + q * NTHR;
                    int r = u >> 3, c8 = u & 7;
                    __align__(16) __half hv[8];
                    if (c8 < 4) {
                        const float* xr = x + ((long)(bm + r) * Ssz + t) * 32 + c8 * 8;
#pragma unroll
                        for (int i = 0; i < 8; i++) {
                            float v = xr[i];
                            if (c8 == 0 && i == 0 && fb) v = sPred[r];
                            hv[i] = __float2half_rn(v);
                        }
                    } else {
#pragma unroll
                        for (int i = 0; i < 8; i++) hv[i] = __ushort_as_half(0);
                        if (c8 == 4) hv[0] = __float2half_rn(fb ? 1.f : 0.f);
                    }
                    *reinterpret_cast<uint4*>(smem + OFF_A + s * 32768 +
                                              swz((u32)(r * 128 + c8 * 16))) =
                        *reinterpret_cast<uint4*>(hv);
                }
            } else {
                CP_WAIT1();
            }
            __syncthreads();

            if (g == 0 || g == 9) {
#pragma unroll
                for (int mf = 0; mf < 4; mf++)
#pragma unroll
                    for (int nf = 0; nf < 2; nf++)
#pragma unroll
                        for (int q = 0; q < 4; q++) acc[mf][nf][q] = 0.f;
            }

            const u32 wB = (g <= 8)  ? sb + OFF_W0R + g * 4096
                         : (g <= 16) ? sb + OFF_W1R + (g - 1) * 4096
                                     : sb + OFF_W1R + (g - 17) * 4096;
            mma_tiles(aB, wB);

            if (g == 7 && t > 0 && !fb) {
                barwait(&d_barB[mrow], 64u * (u32)t);
                // lazy out-projection for step t-1 (own 4 rows)
                if (wid < 4) {
                    int row = n * 4 + wid;
                    const uint4* hp = reinterpret_cast<const uint4*>(
                        h1s + (long)(bm + row) * Hsz);
                    float sv = 0.f;
#pragma unroll
                    for (int h8 = 0; h8 < 2; h8++) {
                        uint4 vv = hp[lane * 2 + h8];
                        const __half2* pp = reinterpret_cast<const __half2*>(&vv);
#pragma unroll
                        for (int q = 0; q < 4; q++) {
                            float2 f2 = __half22float2(pp[q]);
                            int base = lane * 16 + h8 * 8 + q * 2;
                            sv += f2.x * sWo[base] + f2.y * sWo[base + 1];
                        }
                    }
#pragma unroll
                    for (int o = 16; o > 0; o >>= 1)
                        sv += __shfl_down_sync(0xffffffffu, sv, o);
                    if (lane == 0) out[(long)(bm + row) * Ssz + (t - 1)] = sv + bout0;
                }
            }
            if (g == 15) barwait(&d_barA[mrow], 64u * (u32)(t + 1));

            // staging per schedule (always; sources stay valid even past last step)
            if (g < 23)       stageA(g + 2, t, (g + 2 + t) % 3);
            else if (g == 23) stageA(1, t + 1, (t + 2) % 3);
            else              stageA(2, t + 1, (t + 3) % 3);

            if (g == 8) {
                epilogue(c0r, bia0, h0d);
                arrive(&d_barA[mrow]);
            }
            if (g == 24) {
                epilogue(c1r, bia1, h1d);
                arrive(&d_barB[mrow]);
            }
        }
    }

    // final output column (t = Ssz-1)
    barwait(&d_barB[mrow], 64u * (u32)Ssz);
    if (wid < 4) {
        int row = n * 4 + wid;
        const __half* h1f = d_h1[Ssz & 1];
        const uint4* hp = reinterpret_cast<const uint4*>(h1f + (long)(bm + row) * Hsz);
        float sv = 0.f;
#pragma unroll
        for (int h8 = 0; h8 < 2; h8++) {
            uint4 vv = hp[lane * 2 + h8];
            const __half2* pp = reinterpret_cast<const __half2*>(&vv);
#pragma unroll
            for (int q = 0; q < 4; q++) {
                float2 f2 = __half22float2(pp[q]);
                int base = lane * 16 + h8 * 8 + q * 2;
                sv += f2.x * sWo[base] + f2.y * sWo[base + 1];
            }
        }
#pragma unroll
        for (int o = 16; o > 0; o >>= 1) sv += __shfl_down_sync(0xffffffffu, sv, o);
        if (lane == 0) out[(long)(bm + row) * Ssz + (Ssz - 1)] = sv + bout0;
    }
}

// ---------------- launch ------------------------------------------------------
extern "C" void kernel_launch(void* const* d_in, const int* in_sizes, int n_in,
                              void* d_out, int out_size) {
    const float* x    = (const float*)d_in[0];
    const float* Wih0 = (const float*)d_in[1];
    const float* Whh0 = (const float*)d_in[2];
    const float* bih0 = (const float*)d_in[3];
    const float* bhh0 = (const float*)d_in[4];
    const float* Wih1 = (const float*)d_in[5];
    const float* Whh1 = (const float*)d_in[6];
    const float* bih1 = (const float*)d_in[7];
    const float* bhh1 = (const float*)d_in[8];
    const float* Wout = (const float*)d_in[9];
    const float* bout = (const float*)d_in[10];
    float* out = (float*)d_out;

    cudaFuncSetAttribute(run_all, cudaFuncAttributeMaxDynamicSharedMemorySize, SMEM_BYTES);
    init_all<<<1024, 256>>>(Wih0, Whh0, bih0, bhh0, Wih1, Whh1, bih1, bhh1);
    run_all<<<dim3(Gn, Gm), NTHR, SMEM_BYTES>>>(x, Wout, bout, out);
}

// round 10
// speedup vs baseline: 7.1118x; 1.1793x over previous
#include <cuda_runtime.h>
#include <cuda_fp16.h>

typedef unsigned long long u64;
typedef unsigned int u32;

#define Bsz  512
#define Ssz  2688
#define WEEK 672
#define Hsz  512
#define Gn   32
#define Gm   4
#define NTHR 256
#define K0   576
#define K1   1024

// ---- smem layout (bytes) ----
#define OFF_W1R   0             // 16 tiles x 8KB = 131072
#define OFF_FEATW 131072        // 8192
#define OFF_A     139264        // 3 stages x 24576 (A 16KB + W0 slot 8KB)
#define STAGE_STRIDE 24576
#define OFF_WOUT  212992        // 512 f32
#define OFF_SPRED 215040        // 128 f32
#define SMEM_BYTES 215552

// ---------------- persistent device state (no allocation) -------------------
__device__ __half d_W0f[2048 * K0];
__device__ __half d_W1f[2048 * K1];
__device__ __half d_h0[2][Bsz * Hsz];
__device__ __half d_h1[2][Bsz * Hsz];
__device__ float  d_bs0[2048], d_bs1[2048];     // permuted gc' = j*4+g
__device__ unsigned d_barA[Gm], d_barB[Gm];

__device__ __forceinline__ u32 swz(u32 off) { return off ^ ((off >> 3) & 0x70); }
__device__ __forceinline__ float fsig(float x) {
    return __fdividef(1.f, 1.f + __expf(-x));
}
__device__ __forceinline__ float ftanh(float x) {
    float e = __expf(-2.f * x);
    return __fdividef(1.f - e, 1.f + e);
}

__device__ __forceinline__ void ldsm4(u32 a, u32& r0, u32& r1, u32& r2, u32& r3) {
    asm volatile("ldmatrix.sync.aligned.m8n8.x4.shared.b16 {%0,%1,%2,%3}, [%4];"
                 : "=r"(r0), "=r"(r1), "=r"(r2), "=r"(r3) : "r"(a));
}
__device__ __forceinline__ void mma16816(float* d, const u32* a, u32 b0, u32 b1) {
    asm volatile(
        "mma.sync.aligned.m16n8k16.row.col.f32.f16.f16.f32 "
        "{%0,%1,%2,%3}, {%4,%5,%6,%7}, {%8,%9}, {%0,%1,%2,%3};"
        : "+f"(d[0]), "+f"(d[1]), "+f"(d[2]), "+f"(d[3])
        : "r"(a[0]), "r"(a[1]), "r"(a[2]), "r"(a[3]), "r"(b0), "r"(b1));
}
__device__ __forceinline__ void cpa16(u32 dst, const void* src) {
    asm volatile("cp.async.cg.shared.global [%0], [%1], 16;" :: "r"(dst), "l"(src));
}
#define CP_COMMIT() asm volatile("cp.async.commit_group;" ::: "memory")
#define CP_WAIT1()  asm volatile("cp.async.wait_group 1;" ::: "memory")
#define CP_WAIT0()  asm volatile("cp.async.wait_group 0;" ::: "memory")

// ---------------- init --------------------------------------------------------
__global__ void init_all(const float* __restrict__ Wih0, const float* __restrict__ Whh0,
                         const float* __restrict__ bih0, const float* __restrict__ bhh0,
                         const float* __restrict__ Wih1, const float* __restrict__ Whh1,
                         const float* __restrict__ bih1, const float* __restrict__ bhh1) {
    long i0 = (long)blockIdx.x * blockDim.x + threadIdx.x;
    long stride = (long)gridDim.x * blockDim.x;
    for (long i = i0; i < 2048L * K0; i += stride) {
        int gc = (int)(i / K0), k = (int)(i % K0);
        int j = gc >> 2, g = gc & 3, row = g * 512 + j;
        float w = 0.f;
        if (k < 33)       w = Wih0[row * 33 + k];
        else if (k >= 64) w = Whh0[row * 512 + (k - 64)];
        d_W0f[i] = __float2half_rn(w);
    }
    for (long i = i0; i < 2048L * K1; i += stride) {
        int gc = (int)(i / K1), k = (int)(i % K1);
        int j = gc >> 2, g = gc & 3, row = g * 512 + j;
        float w = (k < 512) ? Wih1[row * 512 + k] : Whh1[row * 512 + (k - 512)];
        d_W1f[i] = __float2half_rn(w);
    }
    for (long i = i0; i < 2048; i += stride) {
        int j = (int)(i >> 2), g = (int)(i & 3), row = g * 512 + j;
        d_bs0[i] = bih0[row] + bhh0[row];
        d_bs1[i] = bih1[row] + bhh1[row];
    }
    const __half z = __float2half_rn(0.f);
    for (long i = i0; i < (long)Bsz * Hsz; i += stride) {
        d_h0[0][i] = z; d_h0[1][i] = z; d_h1[0][i] = z; d_h1[1][i] = z;
    }
    if (i0 < Gm) { d_barA[i0] = 0u; d_barB[i0] = 0u; }
}

// ---------------- the persistent kernel --------------------------------------
__global__ void __launch_bounds__(NTHR, 1) run_all(
    const float* __restrict__ x, const float* __restrict__ Wout,
    const float* __restrict__ bout, float* __restrict__ out) {
    extern __shared__ __align__(128) char smem[];
    const int tid = threadIdx.x, wid = tid >> 5, lane = tid & 31;
    const int n = blockIdx.x, mrow = blockIdx.y;
    const int bm = mrow * 128;
    const u32 sb = (u32)__cvta_generic_to_shared(smem);
    const float bout0 = bout[0];

    const int warp_m = (wid >> 2) * 64;          // 2 m-groups
    const int warp_n = (wid & 3) * 16;           // 4 n-groups of 16 gc
    const u32 aswz0 = swz((u32)((warp_m + (lane & 7) + ((lane >> 3) & 1) * 8) * 128
                                + (lane >> 4) * 16));
    const u32 bswz0 = swz((u32)((warp_n + (lane & 7) + (lane >> 4) * 8) * 128
                                + ((lane >> 3) & 1) * 16));
    const int jl0 = (warp_n >> 2) + ((lane & 3) >> 1);
    float4 bia0[2], bia1[2];
    bia0[0] = *reinterpret_cast<const float4*>(&d_bs0[n * 64 + jl0 * 4]);
    bia0[1] = *reinterpret_cast<const float4*>(&d_bs0[n * 64 + (jl0 + 2) * 4]);
    bia1[0] = *reinterpret_cast<const float4*>(&d_bs1[n * 64 + jl0 * 4]);
    bia1[1] = *reinterpret_cast<const float4*>(&d_bs1[n * 64 + (jl0 + 2) * 4]);

    // precomputed staging offsets (registers)
    const int c8 = tid & 7, r0 = tid >> 3;
    u32 soffA[4]; int goffA[4];
    u32 soffW[2]; int goffW[2];
#pragma unroll
    for (int q = 0; q < 4; q++) {
        int r = r0 + q * 32;
        soffA[q] = swz((u32)(r * 128 + c8 * 16));
        goffA[q] = (bm + r) * Hsz + c8 * 8;
    }
#pragma unroll
    for (int q = 0; q < 2; q++) {
        int rr = r0 + q * 32;
        soffW[q] = swz((u32)(rr * 128 + c8 * 16));
        goffW[q] = (n * 64 + rr) * K0 + c8 * 8;
    }

    float* sWo = reinterpret_cast<float*>(smem + OFF_WOUT);
    float* sPred = reinterpret_cast<float*>(smem + OFF_SPRED);
    for (int i = tid; i < 512; i += NTHR) sWo[i] = Wout[i];

    // ---- resident weights: W1 (16 tiles) + feature W0 tile ----
#pragma unroll
    for (int q = 0; q < 32; q++) {
        int u = tid + q * NTHR;
        int tile = u >> 9, w = u & 511, rr = w >> 3, cc = w & 7;
        cpa16(sb + OFF_W1R + tile * 8192 + swz((u32)(rr * 128 + cc * 16)),
              d_W1f + (long)(n * 64 + rr) * K1 + tile * 64 + cc * 8);
    }
#pragma unroll
    for (int q = 0; q < 2; q++) {
        int rr = r0 + q * 32;
        cpa16(sb + OFF_FEATW + soffW[q], d_W0f + (long)(n * 64 + rr) * K0 + c8 * 8);
    }
    CP_COMMIT(); CP_WAIT0();
    __syncthreads();

    float acc[4][2][4];
    float c0r[4][2], c1r[4][2];
#pragma unroll
    for (int mf = 0; mf < 4; mf++)
#pragma unroll
        for (int nf = 0; nf < 2; nf++) { c0r[mf][nf] = 0.f; c1r[mf][nf] = 0.f; }

    // stage chunk c of step tt into slot (c+tt)%3.
    // c 0..7: A=h0_old k c*64, + stream W0 tile c+1 ; c 8: feature (STS later, empty group)
    // c 9..16: A=h1_old ; c 17..24: A=h0_new
    auto stageChunk = [&](int c, int tt) {
        if (c == 8) { CP_COMMIT(); return; }   // placeholder group for accounting
        u32 base = sb + OFF_A + ((c + tt) % 3) * STAGE_STRIDE;
        const __half* src;
        int kc;
        if (c < 8)       { src = d_h0[tt & 1];       kc = c * 64; }
        else if (c < 17) { src = d_h1[tt & 1];       kc = (c - 9) * 64; }
        else             { src = d_h0[(tt & 1) ^ 1]; kc = (c - 17) * 64; }
#pragma unroll
        for (int q = 0; q < 4; q++)
            cpa16(base + soffA[q], src + kc + goffA[q]);
        if (c < 8) {
            const __half* wsrc = d_W0f + (c + 1) * 64;
#pragma unroll
            for (int q = 0; q < 2; q++)
                cpa16(base + 16384 + soffW[q], wsrc + goffW[q]);
        }
        CP_COMMIT();
    };
    auto mma_tiles = [&](u32 aB, u32 wB) {
#pragma unroll
        for (int kkl = 0; kkl < 4; kkl++) {
            const u32 a_sw = aswz0 ^ (u32)(kkl * 32);
            const u32 b_sw = bswz0 ^ (u32)(kkl * 32);
            u32 ah[4][4], bh[4];
#pragma unroll
            for (int mf = 0; mf < 4; mf++)
                ldsm4(aB + a_sw + mf * 2048, ah[mf][0], ah[mf][1], ah[mf][2], ah[mf][3]);
            ldsm4(wB + b_sw, bh[0], bh[1], bh[2], bh[3]);
#pragma unroll
            for (int mf = 0; mf < 4; mf++)
#pragma unroll
                for (int nf = 0; nf < 2; nf++)
                    mma16816(&acc[mf][nf][0], ah[mf], bh[nf * 2], bh[nf * 2 + 1]);
        }
    };
    auto epilogue = [&](float cre[4][2], const float4* bia, __half* __restrict__ hdst) {
        const bool od = (lane & 1);
        const int rbase = warp_m + (lane >> 2) + (od ? 8 : 0);
#pragma unroll
        for (int mf = 0; mf < 4; mf++)
#pragma unroll
            for (int nf = 0; nf < 2; nf++) {
                float d0 = acc[mf][nf][0], d1 = acc[mf][nf][1];
                float d2 = acc[mf][nf][2], d3 = acc[mf][nf][3];
                float v1 = __shfl_xor_sync(0xffffffffu, od ? d0 : d2, 1);
                float v2 = __shfl_xor_sync(0xffffffffu, od ? d1 : d3, 1);
                float gi = od ? v1 : d0;
                float gf = od ? v2 : d1;
                float gg = od ? d2 : v1;
                float go = od ? d3 : v2;
                float iv = fsig(gi + bia[nf].x);
                float fv = fsig(gf + bia[nf].y);
                float gv = ftanh(gg + bia[nf].z);
                float ov = fsig(go + bia[nf].w);
                float cn = fv * cre[mf][nf] + iv * gv;
                cre[mf][nf] = cn;
                int row = rbase + mf * 16;
                int col = n * 16 + jl0 + nf * 2;
                hdst[(long)(bm + row) * Hsz + col] = __float2half_rn(ov * ftanh(cn));
            }
    };
    auto barwait = [&](unsigned* ctr, unsigned target) {
        if (tid == 0) {
            unsigned cur;
            do {
                asm volatile("ld.acquire.gpu.u32 %0, [%1];"
                             : "=r"(cur) : "l"(ctr) : "memory");
            } while (cur < target);
        }
        __syncthreads();
    };
    auto arrive = [&](unsigned* ctr) {
        __syncthreads();
        if (tid == 0) {
            unsigned old, one = 1u;
            asm volatile("atom.release.gpu.add.u32 %0, [%1], %2;"
                         : "=r"(old) : "l"(ctr), "r"(one) : "memory");
        }
    };
    auto lazy_out = [&](const __half* __restrict__ h1s, int tw) {
        if (wid < 4) {
            int row = n * 4 + wid;
            const uint4* hp = reinterpret_cast<const uint4*>(h1s + (long)(bm + row) * Hsz);
            float sv = 0.f;
#pragma unroll
            for (int h8 = 0; h8 < 2; h8++) {
                uint4 vv = hp[lane * 2 + h8];
                const __half2* pp = reinterpret_cast<const __half2*>(&vv);
#pragma unroll
                for (int q = 0; q < 4; q++) {
                    float2 f2 = __half22float2(pp[q]);
                    int base = lane * 16 + h8 * 8 + q * 2;
                    sv += f2.x * sWo[base] + f2.y * sWo[base + 1];
                }
            }
#pragma unroll
            for (int o = 16; o > 0; o >>= 1) sv += __shfl_down_sync(0xffffffffu, sv, o);
            if (lane == 0) out[(long)(bm + row) * Ssz + tw] = sv + bout0;
        }
    };

    // prologue: stage chunks 0,1 of step 0
    stageChunk(0, 0);
    stageChunk(1, 0);

#pragma unroll 1
    for (int t = 0; t < Ssz; t++) {
        const bool fb = (((t / WEEK) & 1) == 1);
        const __half* h1s = d_h1[t & 1];
        __half* h0d = d_h0[(t & 1) ^ 1];
        __half* h1d = d_h1[(t & 1) ^ 1];

#pragma unroll 1
        for (int g = 0; g < 25; g++) {
            const u32 aB = sb + OFF_A + ((g + t) % 3) * STAGE_STRIDE;
            CP_WAIT1();
            if (g == 8) {
                if (fb) {   // predictions for step t-1 (h1s ready: barB waited at g==7)
                    int r = tid >> 1, hf = tid & 1;
                    const uint4* hp = reinterpret_cast<const uint4*>(
                        h1s + (long)(bm + r) * Hsz) + hf * 32;
                    float sv = 0.f;
#pragma unroll 8
                    for (int i = 0; i < 32; i++) {
                        uint4 vv = hp[i];
                        const __half2* pp = reinterpret_cast<const __half2*>(&vv);
#pragma unroll
                        for (int q = 0; q < 4; q++) {
                            float2 f2 = __half22float2(pp[q]);
                            int base = hf * 256 + i * 8 + q * 2;
                            sv += f2.x * sWo[base] + f2.y * sWo[base + 1];
                        }
                    }
                    sv += __shfl_xor_sync(0xffffffffu, sv, 1);
                    if (hf == 0) {
                        float val = sv + bout0;
                        sPred[r] = val;
                        if ((r >> 2) == n) out[(long)(bm + r) * Ssz + (t - 1)] = val;
                    }
                    __syncthreads();
                }
                // stage features (STS) into this chunk's slot
#pragma unroll
                for (int q = 0; q < 4; q++) {
                    int r = r0 + q * 32;
                    __align__(16) __half hv[8];
                    if (c8 < 4) {
                        const float* xr = x + ((long)(bm + r) * Ssz + t) * 32 + c8 * 8;
#pragma unroll
                        for (int i = 0; i < 8; i++) {
                            float v = xr[i];
                            if (c8 == 0 && i == 0 && fb) v = sPred[r];
                            hv[i] = __float2half_rn(v);
                        }
                    } else {
#pragma unroll
                        for (int i = 0; i < 8; i++) hv[i] = __ushort_as_half(0);
                        if (c8 == 4) hv[0] = __float2half_rn(fb ? 1.f : 0.f);
                    }
                    *reinterpret_cast<uint4*>(smem + (aB - sb) + soffA[q]) =
                        *reinterpret_cast<uint4*>(hv);
                }
            }
            __syncthreads();

            if (g == 0 || g == 9) {
#pragma unroll
                for (int mf = 0; mf < 4; mf++)
#pragma unroll
                    for (int nf = 0; nf < 2; nf++)
#pragma unroll
                        for (int q = 0; q < 4; q++) acc[mf][nf][q] = 0.f;
            }

            const u32 wB = (g < 8)   ? aB + 16384
                         : (g == 8)  ? sb + OFF_FEATW
                         : (g <= 16) ? sb + OFF_W1R + (g - 1) * 8192
                                     : sb + OFF_W1R + (g - 17) * 8192;
            mma_tiles(aB, wB);

            if (g == 7 && t > 0) {
                barwait(&d_barB[mrow], 32u * (u32)t);
                if (!fb) lazy_out(h1s, t - 1);
            }
            if (g == 15) barwait(&d_barA[mrow], 32u * (u32)(t + 1));

            if (g < 23)       stageChunk(g + 2, t);
            else if (g == 23) stageChunk(0, t + 1);
            else              stageChunk(1, t + 1);

            if (g == 8) {
                epilogue(c0r, bia0, h0d);
                arrive(&d_barA[mrow]);
            }
            if (g == 24) {
                epilogue(c1r, bia1, h1d);
                arrive(&d_barB[mrow]);
            }
        }
    }

    // final output column (t = Ssz-1)
    barwait(&d_barB[mrow], 32u * (u32)Ssz);
    lazy_out(d_h1[Ssz & 1], Ssz - 1);
}

// ---------------- launch ------------------------------------------------------
extern "C" void kernel_launch(void* const* d_in, const int* in_sizes, int n_in,
                              void* d_out, int out_size) {
    const float* x    = (const float*)d_in[0];
    const float* Wih0 = (const float*)d_in[1];
    const float* Whh0 = (const float*)d_in[2];
    const float* bih0 = (const float*)d_in[3];
    const float* bhh0 = (const float*)d_in[4];
    const float* Wih1 = (const float*)d_in[5];
    const float* Whh1 = (const float*)d_in[6];
    const float* bih1 = (const float*)d_in[7];
    const float* bhh1 = (const float*)d_in[8];
    const float* Wout = (const float*)d_in[9];
    const float* bout = (const float*)d_in[10];
    float* out = (float*)d_out;

    cudaFuncSetAttribute(run_all, cudaFuncAttributeMaxDynamicSharedMemorySize, SMEM_BYTES);
    init_all<<<1024, 256>>>(Wih0, Whh0, bih0, bhh0, Wih1, Whh1, bih1, bhh1);
    run_all<<<dim3(Gn, Gm), NTHR, SMEM_BYTES>>>(x, Wout, bout, out);
}